// round 1
// baseline (speedup 1.0000x reference)
#include <cuda_runtime.h>
#include <cstdint>

// Scalar accumulator in device global memory (no allocations allowed).
__device__ double g_acc;

__global__ void moonloss_zero_kernel() {
    g_acc = 0.0;
}

__device__ __forceinline__ float moon_term(float x, float t, bool circ) {
    // out = circ ? floor-mod(x, 1) : x
    float o = circ ? (x - floorf(x)) : x;
    float d = o - t;
    if (circ && (fabsf(d) > 0.5f)) {
        // shift = (t < o) ? +1 : -1 ; diff = o - (t + shift) = d - shift
        d += (t < o) ? -1.0f : 1.0f;
    }
    return d * d;
}

__global__ void __launch_bounds__(256) moonloss_main_kernel(
    const float4* __restrict__ out4,
    const float4* __restrict__ tgt4,
    unsigned int n4)
{
    const unsigned int stride = gridDim.x * blockDim.x;
    double local = 0.0;

    for (unsigned int v = blockIdx.x * blockDim.x + threadIdx.x; v < n4; v += stride) {
        float4 o = out4[v];
        float4 t = tgt4[v];

        // linear base index of this vector = 4*v ; column = idx % 5
        unsigned int base = 4u * v;
        unsigned int col = base % 5u;

        float s = 0.0f;

        // lane 0
        s += moon_term(o.x, t.x, col != 0u);
        col = (col == 4u) ? 0u : col + 1u;
        // lane 1
        s += moon_term(o.y, t.y, col != 0u);
        col = (col == 4u) ? 0u : col + 1u;
        // lane 2
        s += moon_term(o.z, t.z, col != 0u);
        col = (col == 4u) ? 0u : col + 1u;
        // lane 3
        s += moon_term(o.w, t.w, col != 0u);

        local += (double)s;
    }

    // Warp reduce (double via two 32-bit shuffles handled by compiler intrinsic)
    #pragma unroll
    for (int off = 16; off > 0; off >>= 1)
        local += __shfl_down_sync(0xFFFFFFFFu, local, off);

    __shared__ double warp_sums[8];  // 256 threads = 8 warps
    int lane = threadIdx.x & 31;
    int wid  = threadIdx.x >> 5;
    if (lane == 0) warp_sums[wid] = local;
    __syncthreads();

    if (wid == 0) {
        double b = (lane < 8) ? warp_sums[lane] : 0.0;
        #pragma unroll
        for (int off = 4; off > 0; off >>= 1)
            b += __shfl_down_sync(0xFFFFFFFFu, b, off);
        if (lane == 0)
            atomicAdd(&g_acc, b);
    }
}

__global__ void moonloss_finalize_kernel(float* __restrict__ out, double inv_n) {
    out[0] = (float)(g_acc * inv_n);
}

extern "C" void kernel_launch(void* const* d_in, const int* in_sizes, int n_in,
                              void* d_out, int out_size)
{
    const float* outputs = (const float*)d_in[0];
    const float* targets = (const float*)d_in[1];
    float* out = (float*)d_out;

    const long long n_elems = (long long)in_sizes[0];   // B * F = 41,943,040
    const unsigned int n4 = (unsigned int)(n_elems / 4);

    moonloss_zero_kernel<<<1, 1>>>();

    const int threads = 256;
    const int blocks = 148 * 8;  // full chip, ~35 grid-stride iterations/thread
    moonloss_main_kernel<<<blocks, threads>>>(
        (const float4*)outputs, (const float4*)targets, n4);

    moonloss_finalize_kernel<<<1, 1>>>(out, 1.0 / (double)n_elems);
}